// round 1
// baseline (speedup 1.0000x reference)
#include <cuda_runtime.h>
#include <cuda_bf16.h>
#include <cstdint>

#define DDIM 768
#define KCB  2048
#define NTOK 16384   // B*T = 8*2048
#define BM 64
#define BN 64
#define BK 16

// Scratch (no allocations allowed)
__device__ float g_half_esq[KCB];
__device__ int   g_indices[NTOK];
__device__ float g_row_partial[NTOK];

// ---------------------------------------------------------------------------
// Kernel A: half_esq[k] = 0.5 * sum_d codebook[k][d]^2
// ---------------------------------------------------------------------------
__global__ void esq_kernel(const float* __restrict__ cb) {
    int k = blockIdx.x;
    const float* row = cb + (size_t)k * DDIM;
    float s = 0.f;
    for (int d = threadIdx.x; d < DDIM; d += 256) {
        float v = row[d];
        s += v * v;
    }
    // warp reduce
    #pragma unroll
    for (int off = 16; off > 0; off >>= 1)
        s += __shfl_down_sync(0xFFFFFFFFu, s, off);
    __shared__ float warp_s[8];
    int wid = threadIdx.x >> 5, lid = threadIdx.x & 31;
    if (lid == 0) warp_s[wid] = s;
    __syncthreads();
    if (threadIdx.x == 0) {
        float t = 0.f;
        #pragma unroll
        for (int w = 0; w < 8; w++) t += warp_s[w];
        g_half_esq[k] = 0.5f * t;
    }
}

// ---------------------------------------------------------------------------
// Kernel B: fused GEMM + argmax of (x.e - 0.5||e||^2) over k
// BM=64 token rows per block, loop over all K in BN=64 chunks, BK=16 deep.
// 256 threads as 16x16, each owns a 4x4 register tile.
// ---------------------------------------------------------------------------
__global__ __launch_bounds__(256) void dist_argmin_kernel(
    const float* __restrict__ token, const float* __restrict__ cb)
{
    __shared__ float As[BK * BM];      // transposed: As[p*BM + row]
    __shared__ float Bs[BK * BN];      // transposed: Bs[p*BN + col]
    __shared__ float s_val[BM * 16];
    __shared__ int   s_idx[BM * 16];

    const int rowBase = blockIdx.x * BM;
    const int tid = threadIdx.x;
    const int tx = tid & 15;           // col group
    const int ty = tid >> 4;           // row group

    const int ldr = tid >> 2;          // 0..63  (row within tile for loading)
    const int ldv = tid & 3;           // 0..3   (which float4 of the 16-wide K slab)

    float best[4];
    int   bidx[4];
    #pragma unroll
    for (int i = 0; i < 4; i++) { best[i] = -3.4e38f; bidx[i] = 0x7FFFFFFF; }

    for (int nb = 0; nb < KCB; nb += BN) {
        float acc[4][4];
        #pragma unroll
        for (int i = 0; i < 4; i++)
            #pragma unroll
            for (int c = 0; c < 4; c++) acc[i][c] = 0.f;

        for (int kk = 0; kk < DDIM; kk += BK) {
            // Load A tile (64 rows x 16), transpose into smem
            float4 a4 = *reinterpret_cast<const float4*>(
                token + (size_t)(rowBase + ldr) * DDIM + kk + ldv * 4);
            As[(ldv * 4 + 0) * BM + ldr] = a4.x;
            As[(ldv * 4 + 1) * BM + ldr] = a4.y;
            As[(ldv * 4 + 2) * BM + ldr] = a4.z;
            As[(ldv * 4 + 3) * BM + ldr] = a4.w;
            // Load B tile (64 codebook rows x 16), transpose into smem
            float4 b4 = *reinterpret_cast<const float4*>(
                cb + (size_t)(nb + ldr) * DDIM + kk + ldv * 4);
            Bs[(ldv * 4 + 0) * BN + ldr] = b4.x;
            Bs[(ldv * 4 + 1) * BN + ldr] = b4.y;
            Bs[(ldv * 4 + 2) * BN + ldr] = b4.z;
            Bs[(ldv * 4 + 3) * BN + ldr] = b4.w;
            __syncthreads();

            #pragma unroll
            for (int p = 0; p < BK; p++) {
                float4 a = *reinterpret_cast<const float4*>(&As[p * BM + ty * 4]);
                float4 b = *reinterpret_cast<const float4*>(&Bs[p * BN + tx * 4]);
                float av[4] = {a.x, a.y, a.z, a.w};
                float bv[4] = {b.x, b.y, b.z, b.w};
                #pragma unroll
                for (int i = 0; i < 4; i++)
                    #pragma unroll
                    for (int c = 0; c < 4; c++)
                        acc[i][c] += av[i] * bv[c];
            }
            __syncthreads();
        }

        // Fold in -0.5||e||^2 and update running argmax (tie -> lowest index,
        // matching jnp.argmin's first-occurrence rule)
        #pragma unroll
        for (int c = 0; c < 4; c++) {
            int kidx = nb + tx * 4 + c;
            float he = g_half_esq[kidx];
            #pragma unroll
            for (int i = 0; i < 4; i++) {
                float s = acc[i][c] - he;
                if (s > best[i] || (s == best[i] && kidx < bidx[i])) {
                    best[i] = s; bidx[i] = kidx;
                }
            }
        }
    }

    // Cross-thread (over tx) argmax reduction per row
    #pragma unroll
    for (int i = 0; i < 4; i++) {
        int r = ty * 4 + i;
        s_val[r * 16 + tx] = best[i];
        s_idx[r * 16 + tx] = bidx[i];
    }
    __syncthreads();
    if (tid < BM) {
        int r = tid;
        float bv = s_val[r * 16];
        int   bi = s_idx[r * 16];
        #pragma unroll
        for (int j = 1; j < 16; j++) {
            float v = s_val[r * 16 + j];
            int   ix = s_idx[r * 16 + j];
            if (v > bv || (v == bv && ix < bi)) { bv = v; bi = ix; }
        }
        g_indices[rowBase + r] = bi;
    }
}

// ---------------------------------------------------------------------------
// Kernel C: gather codebook[idx] -> out, per-row sum of (q-x)^2, write indices
// ---------------------------------------------------------------------------
__global__ void gather_kernel(const float* __restrict__ token,
                              const float* __restrict__ cb,
                              float* __restrict__ out,
                              int write_indices)
{
    int row = blockIdx.x;
    int idx = g_indices[row];
    const float* q = cb + (size_t)idx * DDIM;
    const float* x = token + (size_t)row * DDIM;
    float* o = out + (size_t)row * DDIM;
    float s = 0.f;
    for (int d = threadIdx.x; d < DDIM; d += 256) {
        float qv = q[d];
        float xv = x[d];
        o[d] = qv;                    // quantized == codebook[idx] numerically
        float df = qv - xv;
        s += df * df;
    }
    #pragma unroll
    for (int off = 16; off > 0; off >>= 1)
        s += __shfl_down_sync(0xFFFFFFFFu, s, off);
    __shared__ float warp_s[8];
    int wid = threadIdx.x >> 5, lid = threadIdx.x & 31;
    if (lid == 0) warp_s[wid] = s;
    __syncthreads();
    if (threadIdx.x == 0) {
        float t = 0.f;
        #pragma unroll
        for (int w = 0; w < 8; w++) t += warp_s[w];
        g_row_partial[row] = t;
        if (write_indices)
            out[(size_t)NTOK * DDIM + row] = (float)idx;
    }
}

// ---------------------------------------------------------------------------
// Kernel D: deterministic reduce of row partials -> commit loss
// ---------------------------------------------------------------------------
__global__ void loss_kernel(float* __restrict__ out, long long out_size) {
    __shared__ float sm[1024];
    float s = 0.f;
    for (int i = threadIdx.x; i < NTOK; i += 1024) s += g_row_partial[i];
    sm[threadIdx.x] = s;
    __syncthreads();
    for (int off = 512; off > 0; off >>= 1) {
        if (threadIdx.x < off) sm[threadIdx.x] += sm[threadIdx.x + off];
        __syncthreads();
    }
    if (threadIdx.x == 0) {
        long long pos = (long long)NTOK * DDIM + NTOK;
        if (out_size > pos)
            out[pos] = sm[0] / (float)((long long)NTOK * DDIM);
    }
}

__global__ void fill_zero_kernel(float* __restrict__ p, long long n) {
    long long i = (long long)blockIdx.x * blockDim.x + threadIdx.x;
    if (i < n) p[i] = 0.f;
}

// ---------------------------------------------------------------------------
extern "C" void kernel_launch(void* const* d_in, const int* in_sizes, int n_in,
                              void* d_out, int out_size)
{
    const float* token = (const float*)d_in[0];
    const float* cb    = (const float*)d_in[1];
    // Defensive: detect swapped input order by element counts
    if (n_in >= 2 && in_sizes[0] == KCB * DDIM && in_sizes[1] == NTOK * DDIM) {
        const float* t = token; token = cb; cb = t;
    }
    float* out = (float*)d_out;

    esq_kernel<<<KCB, 256>>>(cb);
    dist_argmin_kernel<<<NTOK / BM, 256>>>(token, cb);

    long long osz = (long long)out_size;
    int write_indices = (osz >= (long long)NTOK * DDIM + NTOK) ? 1 : 0;
    gather_kernel<<<NTOK, 256>>>(token, cb, out, write_indices);
    loss_kernel<<<1, 1024>>>(out, osz);

    // Zero any unexpected tail so poisoned bytes don't leak into comparison
    long long expected = (long long)NTOK * DDIM + NTOK + 1;
    if (osz > expected) {
        long long tail = osz - expected;
        int blocks = (int)((tail + 255) / 256);
        fill_zero_kernel<<<blocks, 256>>>(out + expected, tail);
    }
}